// round 4
// baseline (speedup 1.0000x reference)
#include <cuda_runtime.h>
#include <cstdint>

// ---------------- static device scratch (no runtime allocation) --------------
#define SLAB_SHIFT 15
#define SLAB_ELEMS (1 << SLAB_SHIFT)        // 32768 floats = 128 KB per slab
#define MAX_SLABS  4096                     // covers up to 134M elements
#define MAX_FAULTS (1 << 20)                // covers 671,089 with headroom

__device__ int   g_counts [MAX_SLABS];
__device__ int   g_offsets[MAX_SLABS + 1];
__device__ int   g_cursor [MAX_SLABS];
__device__ int   g_sidx   [MAX_FAULTS];
__device__ float g_sval   [MAX_FAULTS];

// ---------------- pass 0: zero histogram ------------------------------------
__global__ void zero_counts_kernel(int nslabs) {
    int i = blockIdx.x * blockDim.x + threadIdx.x;
    if (i < nslabs) g_counts[i] = 0;
}

// ---------------- pass 1: histogram of fault slabs (smem-local) --------------
__global__ void hist_kernel(const int* __restrict__ idx, int n, int nslabs) {
    __shared__ int sh[MAX_SLABS];
    for (int i = threadIdx.x; i < nslabs; i += blockDim.x) sh[i] = 0;
    __syncthreads();

    int t = blockIdx.x * blockDim.x + threadIdx.x;
    int stride = gridDim.x * blockDim.x;
    int nvec = n >> 2;
    for (int v = t; v < nvec; v += stride) {
        int4 d4 = reinterpret_cast<const int4*>(idx)[v];
        atomicAdd(&sh[d4.x >> SLAB_SHIFT], 1);
        atomicAdd(&sh[d4.y >> SLAB_SHIFT], 1);
        atomicAdd(&sh[d4.z >> SLAB_SHIFT], 1);
        atomicAdd(&sh[d4.w >> SLAB_SHIFT], 1);
    }
    // scalar tail handled by thread 0 of block 0
    if (blockIdx.x == 0 && threadIdx.x == 0) {
        for (int i = nvec << 2; i < n; i++) atomicAdd(&sh[idx[i] >> SLAB_SHIFT], 1);
    }
    __syncthreads();
    for (int i = threadIdx.x; i < nslabs; i += blockDim.x) {
        int c = sh[i];
        if (c) atomicAdd(&g_counts[i], c);
    }
}

// ---------------- pass 2: exclusive scan (single block) ----------------------
// nslabs <= 4096; 1024 threads, 4 bins each, Hillis-Steele over partial sums.
__global__ void scan_kernel(int nslabs) {
    __shared__ int part[1024];
    int t = threadIdx.x;
    int base = t * 4;
    int c0 = (base + 0 < nslabs) ? g_counts[base + 0] : 0;
    int c1 = (base + 1 < nslabs) ? g_counts[base + 1] : 0;
    int c2 = (base + 2 < nslabs) ? g_counts[base + 2] : 0;
    int c3 = (base + 3 < nslabs) ? g_counts[base + 3] : 0;
    part[t] = c0 + c1 + c2 + c3;
    __syncthreads();
    // inclusive scan of partial sums
    for (int d = 1; d < 1024; d <<= 1) {
        int v = (t >= d) ? part[t - d] : 0;
        __syncthreads();
        part[t] += v;
        __syncthreads();
    }
    int excl = (t == 0) ? 0 : part[t - 1];
    if (base + 0 <= nslabs) { g_offsets[base + 0] = excl;           g_cursor[base + 0] = excl; }
    excl += c0;
    if (base + 1 <= nslabs) { g_offsets[base + 1] = excl;           if (base + 1 < nslabs) g_cursor[base + 1] = excl; }
    excl += c1;
    if (base + 2 <= nslabs) { g_offsets[base + 2] = excl;           if (base + 2 < nslabs) g_cursor[base + 2] = excl; }
    excl += c2;
    if (base + 3 <= nslabs) { g_offsets[base + 3] = excl;           if (base + 3 < nslabs) g_cursor[base + 3] = excl; }
    excl += c3;
    if (base + 4 <= nslabs) { g_offsets[base + 4] = excl; }
}

// ---------------- pass 3: partition faults into slab buckets -----------------
__global__ void partition_kernel(const int* __restrict__ idx,
                                 const float* __restrict__ vals, int n) {
    int t = blockIdx.x * blockDim.x + threadIdx.x;
    int stride = gridDim.x * blockDim.x;
    for (int i = t; i < n; i += stride) {
        int d = idx[i];
        int p = atomicAdd(&g_cursor[d >> SLAB_SHIFT], 1);
        g_sidx[p] = d;
        g_sval[p] = vals[i];
    }
}

// ---------------- pass 4: fused copy + in-L2 scatter -------------------------
// Block b copies slab b (contiguous 128 KB) then scatters its own faults.
// The fault sectors were just written by this block -> dirty in L2 -> no
// random DRAM RMW traffic at all.
__global__ void __launch_bounds__(256)
fused_copy_scatter_kernel(const float* __restrict__ x,
                          float* __restrict__ out, int numel) {
    long long base = (long long)blockIdx.x << SLAB_SHIFT;
    int lim = numel - (int)base;
    if (lim > SLAB_ELEMS) lim = SLAB_ELEMS;

    if (lim == SLAB_ELEMS) {
        // full, 16B-aligned slab: float4 streaming copy
        const float4* src = reinterpret_cast<const float4*>(x + base);
        float4*       dst = reinterpret_cast<float4*>(out + base);
        #pragma unroll 4
        for (int j = threadIdx.x; j < (SLAB_ELEMS / 4); j += 256)
            dst[j] = src[j];
    } else {
        for (int j = threadIdx.x; j < lim; j += 256)
            out[base + j] = x[base + j];
    }
    __syncthreads();

    int s = g_offsets[blockIdx.x];
    int e = g_offsets[blockIdx.x + 1];
    for (int j = s + threadIdx.x; j < e; j += 256)
        out[g_sidx[j]] = g_sval[j];
}

// ---------------- fallback: serial copy + scatter ----------------------------
__global__ void scatter_all_kernel(const float* __restrict__ vals,
                                   const int* __restrict__ idx,
                                   float* __restrict__ out, int n) {
    int i = blockIdx.x * blockDim.x + threadIdx.x;
    if (i < n) out[idx[i]] = vals[i];
}

extern "C" void kernel_launch(void* const* d_in, const int* in_sizes, int n_in,
                              void* d_out, int out_size) {
    const float* x          = (const float*)d_in[0];
    const float* fault_vals = (const float*)d_in[1];
    const int*   fault_idx  = (const int*)d_in[2];
    float* out = (float*)d_out;

    const int numel   = in_sizes[0];   // 67,108,864
    const int covered = in_sizes[1];   // 671,089

    const int nslabs = (numel + SLAB_ELEMS - 1) >> SLAB_SHIFT;

    if (covered > MAX_FAULTS || nslabs > MAX_SLABS) {
        // out-of-bounds for static scratch: known-correct serial path
        cudaMemcpyAsync(out, x, (size_t)numel * sizeof(float),
                        cudaMemcpyDeviceToDevice, 0);
        scatter_all_kernel<<<(covered + 255) / 256, 256>>>(fault_vals, fault_idx,
                                                           out, covered);
        return;
    }

    zero_counts_kernel<<<(nslabs + 255) / 256, 256>>>(nslabs);
    hist_kernel<<<128, 256>>>(fault_idx, covered, nslabs);
    scan_kernel<<<1, 1024>>>(nslabs);
    partition_kernel<<<256, 256>>>(fault_idx, fault_vals, covered);
    fused_copy_scatter_kernel<<<nslabs, 256>>>(x, out, numel);
}

// round 5
// speedup vs baseline: 1.0531x; 1.0531x over previous
#include <cuda_runtime.h>
#include <cstdint>

// ---------------- static device scratch (zero-initialized at load) -----------
#define SLAB_SHIFT 15
#define SLAB_ELEMS (1 << SLAB_SHIFT)        // 32768 floats = 128 KB per slab
#define MAX_SLABS  4096                     // up to 134M elements
#define CAP        512                      // per-slab bucket capacity
#define MAX_FAULTS (1 << 20)                // 1,048,576 (covers 671,089)

__device__ int   g_count[MAX_SLABS];                 // zero at load; self-restoring
__device__ int   g_bidx [MAX_SLABS * CAP];
__device__ float g_bval [MAX_SLABS * CAP];
__device__ int   g_oflow_n;                          // zero at load; self-restoring
__device__ int   g_oflow_idx[MAX_FAULTS];
__device__ float g_oflow_val[MAX_FAULTS];

// ---------------- pass 1: single-pass bucket partition -----------------------
__device__ __forceinline__ void place_fault(int d, float v) {
    int s = d >> SLAB_SHIFT;
    int c = atomicAdd(&g_count[s], 1);
    if (c < CAP) {
        g_bidx[s * CAP + c] = d;
        g_bval[s * CAP + c] = v;
    } else {
        int o = atomicAdd(&g_oflow_n, 1);
        if (o < MAX_FAULTS) { g_oflow_idx[o] = d; g_oflow_val[o] = v; }
    }
}

__global__ void bucket_partition_kernel(const int* __restrict__ idx,
                                        const float* __restrict__ vals, int n) {
    int t = blockIdx.x * blockDim.x + threadIdx.x;
    int nvec = n >> 2;
    if (t < nvec) {
        int4   d4 = reinterpret_cast<const int4*>(idx)[t];
        float4 v4 = reinterpret_cast<const float4*>(vals)[t];
        place_fault(d4.x, v4.x);
        place_fault(d4.y, v4.y);
        place_fault(d4.z, v4.z);
        place_fault(d4.w, v4.w);
    } else {
        int r = t - nvec;                 // scalar tail, one elem per thread
        int i = (nvec << 2) + r;
        if (i < n) place_fault(idx[i], vals[i]);
    }
}

// ---------------- pass 2: fused copy + in-L2 scatter -------------------------
// Block b copies slab b (contiguous 128 KB), then scatters its own bucketed
// faults. Those lines were just written by this block -> dirty in L2 -> the
// scatter costs no random DRAM RMW. Block then re-zeroes its counter so the
// next graph replay starts clean.
__global__ void __launch_bounds__(256)
fused_copy_scatter_kernel(const float* __restrict__ x,
                          float* __restrict__ out, int numel) {
    int b = blockIdx.x;
    int cnt = g_count[b];                 // read by all threads BEFORE re-zero
    if (cnt > CAP) cnt = CAP;

    long long base = (long long)b << SLAB_SHIFT;
    int lim = numel - (int)base;
    if (lim > SLAB_ELEMS) lim = SLAB_ELEMS;

    if (lim == SLAB_ELEMS) {
        const float4* src = reinterpret_cast<const float4*>(x + base);
        float4*       dst = reinterpret_cast<float4*>(out + base);
        #pragma unroll 8
        for (int j = threadIdx.x; j < (SLAB_ELEMS / 4); j += 256)
            dst[j] = src[j];
    } else {
        for (int j = threadIdx.x; j < lim; j += 256)
            out[base + j] = x[base + j];
    }
    __syncthreads();                      // copy done; also orders cnt reads

    const int boff = b * CAP;
    for (int j = threadIdx.x; j < cnt; j += 256)
        out[g_bidx[boff + j]] = g_bval[boff + j];

    if (threadIdx.x == 0) g_count[b] = 0; // restore state for next replay
}

// ---------------- pass 3: overflow scatter (normally empty) ------------------
__global__ void oflow_scatter_kernel(float* __restrict__ out) {
    int n = g_oflow_n;
    if (n > MAX_FAULTS) n = MAX_FAULTS;
    for (int i = threadIdx.x; i < n; i += blockDim.x)
        out[g_oflow_idx[i]] = g_oflow_val[i];
    __syncthreads();
    if (threadIdx.x == 0) g_oflow_n = 0;  // restore state for next replay
}

// ---------------- fallback: serial copy + scatter ----------------------------
__global__ void scatter_all_kernel(const float* __restrict__ vals,
                                   const int* __restrict__ idx,
                                   float* __restrict__ out, int n) {
    int i = blockIdx.x * blockDim.x + threadIdx.x;
    if (i < n) out[idx[i]] = vals[i];
}

extern "C" void kernel_launch(void* const* d_in, const int* in_sizes, int n_in,
                              void* d_out, int out_size) {
    const float* x          = (const float*)d_in[0];
    const float* fault_vals = (const float*)d_in[1];
    const int*   fault_idx  = (const int*)d_in[2];
    float* out = (float*)d_out;

    const int numel   = in_sizes[0];   // 67,108,864
    const int covered = in_sizes[1];   // 671,089

    const int nslabs = (numel + SLAB_ELEMS - 1) >> SLAB_SHIFT;

    if (covered > MAX_FAULTS || nslabs > MAX_SLABS) {
        cudaMemcpyAsync(out, x, (size_t)numel * sizeof(float),
                        cudaMemcpyDeviceToDevice, 0);
        scatter_all_kernel<<<(covered + 255) / 256, 256>>>(fault_vals, fault_idx,
                                                           out, covered);
        return;
    }

    // pass 1: bucket faults by slab (one element per thread, max parallelism)
    const int pthreads = (covered >> 2) + (covered & 3);
    bucket_partition_kernel<<<(pthreads + 255) / 256, 256>>>(fault_idx,
                                                             fault_vals, covered);
    // pass 2: copy + in-L2 scatter
    fused_copy_scatter_kernel<<<nslabs, 256>>>(x, out, numel);
    // pass 3: overflow (statistically empty; correctness safety net)
    oflow_scatter_kernel<<<1, 256>>>(out);
}